// round 6
// baseline (speedup 1.0000x reference)
#include <cuda_runtime.h>

#define N 512
#define D 512

__device__ float g_u[N * D];   // u[i][h]
__device__ float g_v[N * D];   // v[j][h] (+W0_b folded)
__device__ float g_a[N * N];   // softmax rows

typedef unsigned long long u64;

// ---- packed f32x2 helpers (sm_100+) --------------------------------------
__device__ __forceinline__ void fma2(u64& d, u64 a, u64 b) {
    asm("fma.rn.f32x2 %0, %1, %2, %3;" : "=l"(d) : "l"(a), "l"(b), "l"(d));
}
__device__ __forceinline__ u64 add2(u64 a, u64 b) {
    u64 d; asm("add.rn.f32x2 %0, %1, %2;" : "=l"(d) : "l"(a), "l"(b)); return d;
}
__device__ __forceinline__ u64 pk(float x, float y) {
    u64 d; asm("mov.b64 %0, {%1, %2};" : "=l"(d) : "f"(x), "f"(y)); return d;
}
__device__ __forceinline__ float2 upk(u64 v) {
    float2 d; asm("mov.b64 {%0, %1}, %2;" : "=f"(d.x), "=f"(d.y) : "l"(v)); return d;
}
__device__ __forceinline__ void cpa16(float* dst, const float* src) {
    unsigned sa = (unsigned)__cvta_generic_to_shared(dst);
    asm volatile("cp.async.cg.shared.global [%0], [%1], 16;" :: "r"(sa), "l"(src));
}

// ---------------------------------------------------------------------------
// Kernel A: u,v NT-GEMMs. 64x64 tile, 512 threads (16 warps/SM), thread 2x4,
// cp.async double-buffered 32-k chunks. smem [row][k] stride 36, pack-k FFMA2.
// ---------------------------------------------------------------------------
#define AK 32
#define AST 36

__global__ __launch_bounds__(512) void gemm_uv_kernel(
    const float* __restrict__ he, const float* __restrict__ W,
    const float* __restrict__ b)
{
    __shared__ float as[2][64 * AST];
    __shared__ float bs[2][64 * AST];

    const int which = blockIdx.z;
    const int h0 = blockIdx.x * 64;
    const int i0 = blockIdx.y * 64;
    const int koff = which ? D : 0;
    const int tid = threadIdx.x;
    const int tx = tid & 15;           // h: cols tx + 16c
    const int ty = (tid >> 4) & 31;    // i: rows ty, ty+32

    // loader role: tid<256 -> as (he), tid>=256 -> bs (W)
    const int lt = tid & 255;
    const int lr = lt >> 2;                 // 0..63
    const int lk = (lt & 3) << 2;           // 0,4,8,12
    const float* lsrc = (tid < 256)
        ? he + (size_t)(i0 + lr) * D + lk
        : W + (size_t)(h0 + lr) * (2 * D) + koff + lk;
    float* ldst = (tid < 256) ? &as[0][lr * AST + lk] : &bs[0][lr * AST + lk];

    // prologue: chunk 0
    cpa16(ldst, lsrc);
    cpa16(ldst + 16, lsrc + 16);
    asm volatile("cp.async.commit_group;");

    u64 acc[2][4] = {};

    for (int ch = 0; ch < D / AK; ch++) {
        if (ch + 1 < D / AK) {
            float* d2 = ldst + ((ch + 1) & 1) * 64 * AST;
            const float* s2 = lsrc + (ch + 1) * AK;
            cpa16(d2, s2);
            cpa16(d2 + 16, s2 + 16);
            asm volatile("cp.async.commit_group;");
            asm volatile("cp.async.wait_group 1;");
        } else {
            asm volatile("cp.async.wait_group 0;");
        }
        __syncthreads();

        const float* ab = as[ch & 1];
        const float* bb = bs[ch & 1];
        #pragma unroll
        for (int kk = 0; kk < AK; kk += 4) {
            ulonglong2 av[2], bv[4];
            #pragma unroll
            for (int r = 0; r < 2; r++)
                av[r] = *(const ulonglong2*)&ab[(ty + 32 * r) * AST + kk];
            #pragma unroll
            for (int c = 0; c < 4; c++)
                bv[c] = *(const ulonglong2*)&bb[(tx + 16 * c) * AST + kk];
            #pragma unroll
            for (int r = 0; r < 2; r++)
                #pragma unroll
                for (int c = 0; c < 4; c++) {
                    fma2(acc[r][c], av[r].x, bv[c].x);
                    fma2(acc[r][c], av[r].y, bv[c].y);
                }
        }
        __syncthreads();
    }

    float* out = which ? g_v : g_u;
    #pragma unroll
    for (int r = 0; r < 2; r++) {
        const int row = i0 + ty + 32 * r;
        #pragma unroll
        for (int c = 0; c < 4; c++) {
            const int col = h0 + tx + 16 * c;
            float2 f = upk(acc[r][c]);
            float val = f.x + f.y;
            if (which) val += __ldg(&b[col]);
            out[(size_t)row * D + col] = val;
        }
    }
}

// ---------------------------------------------------------------------------
// Kernel B: pairwise + softmax. CTA = 4 i-rows x 512 j, 512 threads
// (16 warps/SM). Thread = 2 i x 2 j. cp.async double-buffered 32-h v chunks.
// ---------------------------------------------------------------------------
#define HCH 32
#define VST 36
#define NCH (D / HCH)

__global__ __launch_bounds__(512) void pairwise_kernel(
    const float* __restrict__ w1)
{
    extern __shared__ float sm[];
    float* v_s   = sm;                         // [2][512][VST]
    float* u_s   = sm + 2 * 512 * VST;         // [4][512]
    float* w_s   = u_s + 4 * 512;              // [512]
    float* p_s   = w_s + 512;                  // [4][512]
    float* inv_s = p_s + 4 * 512;              // [4]

    const int tid = threadIdx.x;
    const int i0 = blockIdx.x * 4;
    const int g = tid >> 8;                    // i-rows {2g, 2g+1}
    const int j1 = tid & 255;
    const int j2 = j1 + 256;

    // stage u rows + w1
    if (tid < 512) {
        ((float4*)u_s)[tid] = ((const float4*)(g_u + (size_t)i0 * D))[tid];
        if (tid < 128) ((float4*)w_s)[tid] = ((const float4*)w1)[tid];
    }

    // prologue: chunk 0 (512 rows x 32 cols = 4096 f4; 8 per thread)
    for (int m = tid; m < 512 * (HCH / 4); m += 512) {
        const int r = m >> 3, kq = (m & 7) << 2;
        cpa16(v_s + r * VST + kq, g_v + (size_t)r * D + kq);
    }
    asm volatile("cp.async.commit_group;");

    u64 acc[2][2] = {};

    for (int ch = 0; ch < NCH; ch++) {
        if (ch + 1 < NCH) {
            float* buf = v_s + ((ch + 1) & 1) * 512 * VST;
            const float* src = g_v + (ch + 1) * HCH;
            for (int m = tid; m < 512 * (HCH / 4); m += 512) {
                const int r = m >> 3, kq = (m & 7) << 2;
                cpa16(buf + r * VST + kq, src + (size_t)r * D + kq);
            }
            asm volatile("cp.async.commit_group;");
            asm volatile("cp.async.wait_group 1;");
        } else {
            asm volatile("cp.async.wait_group 0;");
        }
        __syncthreads();

        const float* vb = v_s + (ch & 1) * 512 * VST;
        const int cc = ch * HCH;
        #pragma unroll
        for (int kk = 0; kk < HCH; kk += 4) {
            ulonglong2 w2 = *(const ulonglong2*)&w_s[cc + kk];
            ulonglong2 va = *(const ulonglong2*)&vb[j1 * VST + kk];
            ulonglong2 vc = *(const ulonglong2*)&vb[j2 * VST + kk];
            #pragma unroll
            for (int i = 0; i < 2; i++) {
                ulonglong2 u2 = *(const ulonglong2*)&u_s[(2 * g + i) * 512 + cc + kk];
                u64 t; float2 f;
                t = add2(u2.x, va.x); f = upk(t);
                fma2(acc[i][0], pk(fmaxf(f.x, 0.f), fmaxf(f.y, 0.f)), w2.x);
                t = add2(u2.y, va.y); f = upk(t);
                fma2(acc[i][0], pk(fmaxf(f.x, 0.f), fmaxf(f.y, 0.f)), w2.y);
                t = add2(u2.x, vc.x); f = upk(t);
                fma2(acc[i][1], pk(fmaxf(f.x, 0.f), fmaxf(f.y, 0.f)), w2.x);
                t = add2(u2.y, vc.y); f = upk(t);
                fma2(acc[i][1], pk(fmaxf(f.x, 0.f), fmaxf(f.y, 0.f)), w2.y);
            }
        }
        __syncthreads();
    }

    #pragma unroll
    for (int i = 0; i < 2; i++) {
        float2 f = upk(acc[i][0]);
        p_s[(2 * g + i) * 512 + j1] = f.x + f.y;
        f = upk(acc[i][1]);
        p_s[(2 * g + i) * 512 + j2] = f.x + f.y;
    }
    __syncthreads();

    // softmax: warps 0..3 handle rows 0..3
    const int warp = tid >> 5, lane = tid & 31;
    if (warp < 4) {
        float* prow = p_s + warp * 512;
        float m = -1e30f;
        for (int j = lane; j < N; j += 32) m = fmaxf(m, prow[j]);
        #pragma unroll
        for (int o = 16; o; o >>= 1) m = fmaxf(m, __shfl_xor_sync(0xffffffffu, m, o));
        float s = 0.f;
        for (int j = lane; j < N; j += 32) {
            float e = __expf(prow[j] - m);
            prow[j] = e;
            s += e;
        }
        #pragma unroll
        for (int o = 16; o; o >>= 1) s += __shfl_xor_sync(0xffffffffu, s, o);
        if (lane == 0) inv_s[warp] = 1.f / s;
    }
    __syncthreads();

    if (tid < 512) {
        const int i = tid >> 7, jj = tid & 127;
        float4 e = ((const float4*)(p_s + i * 512))[jj];
        const float s = inv_s[i];
        e.x *= s; e.y *= s; e.z *= s; e.w *= s;
        ((float4*)(g_a + (size_t)(i0 + i) * N))[jj] = e;
    }
}

// ---------------------------------------------------------------------------
// Kernel C: out = a @ he. 32x64 tile, 256 threads, pack-k FFMA2, thread 2x4.
// he transposed into smem [c][k] via gather-4-k (conflict-free STS.128).
// ---------------------------------------------------------------------------
#define CK 32
#define CST 36

__global__ __launch_bounds__(256) void out_gemm_kernel(
    const float* __restrict__ he, float* __restrict__ out)
{
    __shared__ float as[32 * CST];   // [i][k]
    __shared__ float bs[64 * CST];   // [c][k]

    const int c0 = blockIdx.x * 64;
    const int i0 = blockIdx.y * 32;
    const int tid = threadIdx.x;
    const int tx = tid & 15;         // c: tx + 16c
    const int ty = tid >> 4;         // i: ty + 16r (0..15)

    u64 acc[2][4] = {};

    for (int k0 = 0; k0 < N; k0 += CK) {
        // a tile: 32 rows x 32 k = 256 f4, 1 per thread
        {
            const int r = tid >> 3, kq = (tid & 7) << 2;
            *(float4*)&as[r * CST + kq] =
                *(const float4*)&g_a[(size_t)(i0 + r) * N + k0 + kq];
        }
        // he tile: gather 4 k's per column, STS.128 along k
        #pragma unroll
        for (int m = tid; m < 512; m += 256) {
            const int c = m & 63;
            const int kb = (m >> 6) << 2;          // 0,4,...,28
            float4 v;
            v.x = he[(size_t)(k0 + kb + 0) * D + c0 + c];
            v.y = he[(size_t)(k0 + kb + 1) * D + c0 + c];
            v.z = he[(size_t)(k0 + kb + 2) * D + c0 + c];
            v.w = he[(size_t)(k0 + kb + 3) * D + c0 + c];
            *(float4*)&bs[c * CST + kb] = v;
        }
        __syncthreads();

        #pragma unroll
        for (int kk = 0; kk < CK; kk += 4) {
            ulonglong2 av[2], bv[4];
            #pragma unroll
            for (int r = 0; r < 2; r++)
                av[r] = *(const ulonglong2*)&as[(ty + 16 * r) * CST + kk];
            #pragma unroll
            for (int c = 0; c < 4; c++)
                bv[c] = *(const ulonglong2*)&bs[(tx + 16 * c) * CST + kk];
            #pragma unroll
            for (int r = 0; r < 2; r++)
                #pragma unroll
                for (int c = 0; c < 4; c++) {
                    fma2(acc[r][c], av[r].x, bv[c].x);
                    fma2(acc[r][c], av[r].y, bv[c].y);
                }
        }
        __syncthreads();
    }

    #pragma unroll
    for (int r = 0; r < 2; r++) {
        const int row = i0 + ty + 16 * r;
        #pragma unroll
        for (int c = 0; c < 4; c++) {
            float2 f = upk(acc[r][c]);
            out[(size_t)row * D + c0 + tx + 16 * c] = f.x + f.y;
        }
    }
}

// ---------------------------------------------------------------------------
extern "C" void kernel_launch(void* const* d_in, const int* in_sizes, int n_in,
                              void* d_out, int out_size)
{
    const float* he  = (const float*)d_in[0];   // (512, 512)
    const float* W0w = (const float*)d_in[1];   // (512, 1024)
    const float* W0b = (const float*)d_in[2];   // (512,)
    const float* W1w = (const float*)d_in[3];   // (1, 512)
    // d_in[4] = W1_b: softmax shift-invariant -> unused
    float* out = (float*)d_out;

    const size_t smemB =
        (size_t)(2 * 512 * VST + 4 * 512 + 512 + 4 * 512 + 8) * sizeof(float);
    cudaFuncSetAttribute(pairwise_kernel,
                         cudaFuncAttributeMaxDynamicSharedMemorySize, (int)smemB);

    dim3 gA(D / 64, N / 64, 2);                  // 128 CTAs x 512 thr
    gemm_uv_kernel<<<gA, 512>>>(he, W0w, W0b);

    pairwise_kernel<<<N / 4, 512, smemB>>>(W1w); // 128 CTAs x 512 thr

    dim3 gC(D / 64, N / 32);                     // 128 CTAs x 256 thr
    out_gemm_kernel<<<gC, 256>>>(he, out);
}

// round 8
// speedup vs baseline: 1.1471x; 1.1471x over previous
#include <cuda_runtime.h>

#define N 512
#define D 512

__device__ float g_u[N * D];            // u[i][h]
__device__ float g_vT[D * N];           // v^T[h][j] (+W0_b folded)
__device__ float g_a[N * N];            // softmax rows
__device__ float g_part[4 * N * 1024];  // k-split partials of [i][n], n<512->u, n>=512->v

typedef unsigned long long u64;

// ---- packed f32x2 helpers (sm_100+) --------------------------------------
__device__ __forceinline__ void fma2(u64& d, u64 a, u64 b) {
    asm("fma.rn.f32x2 %0, %1, %2, %3;" : "=l"(d) : "l"(a), "l"(b), "l"(d));
}
__device__ __forceinline__ u64 add2(u64 a, u64 b) {
    u64 d; asm("add.rn.f32x2 %0, %1, %2;" : "=l"(d) : "l"(a), "l"(b)); return d;
}
__device__ __forceinline__ u64 pk(float x, float y) {
    u64 d; asm("mov.b64 %0, {%1, %2};" : "=l"(d) : "f"(x), "f"(y)); return d;
}
__device__ __forceinline__ float2 upk(u64 v) {
    float2 d; asm("mov.b64 {%0, %1}, %2;" : "=f"(d.x), "=f"(d.y) : "l"(v)); return d;
}
__device__ __forceinline__ void cpa16(float* dst, const float* src) {
    unsigned sa = (unsigned)__cvta_generic_to_shared(dst);
    asm volatile("cp.async.cg.shared.global [%0], [%1], 16;" :: "r"(sa), "l"(src));
}

// ---------------------------------------------------------------------------
// Kernel 1: fused u|v GEMM, k-split 4. Tile 128x128, 256 threads, 8x8/thread
// (k-pair packed FFMA2). grid (8 n-tiles, 4 i-tiles, 4 k-splits) = 128 CTAs.
// Writes partials to g_part[kz][i][n].
// ---------------------------------------------------------------------------
#define GST 36

__global__ __launch_bounds__(256) void uv_gemm_kernel(
    const float* __restrict__ he, const float* __restrict__ W)
{
    extern __shared__ float sm[];
    float* as = sm;                    // [2][128*GST]
    float* bs = sm + 2 * 128 * GST;    // [2][128*GST]

    const int n0 = blockIdx.x * 128;
    const int i0 = blockIdx.y * 128;
    const int kz = blockIdx.z;
    const int kbase = kz * 128;
    const int koff = (n0 >= 512) ? 512 : 0;
    const int nrow0 = n0 & 511;
    const int tid = threadIdx.x;
    const int tx = tid & 15;
    const int ty = tid >> 4;

    // loader mapping: thread covers f4 indices 4*tid .. 4*tid+3 (of 1024)
    const int lr0 = (4 * tid) >> 3;        // 2 f4 per row group
    const int lq0 = (4 * tid) & 7;

    // prologue chunk 0
    #pragma unroll
    for (int q = 0; q < 4; q++) {
        const int f = 4 * tid + q;
        const int r = f >> 3, kq = (f & 7) << 2;
        cpa16(&as[r * GST + kq], &he[(size_t)(i0 + r) * D + kbase + kq]);
        cpa16(&bs[r * GST + kq], &W[(size_t)(nrow0 + r) * (2 * D) + koff + kbase + kq]);
    }
    asm volatile("cp.async.commit_group;");

    u64 acc[8][8] = {};

    for (int ch = 0; ch < 4; ch++) {
        if (ch + 1 < 4) {
            float* ad = as + ((ch + 1) & 1) * 128 * GST;
            float* bd = bs + ((ch + 1) & 1) * 128 * GST;
            const int kc = kbase + (ch + 1) * 32;
            #pragma unroll
            for (int q = 0; q < 4; q++) {
                const int f = 4 * tid + q;
                const int r = f >> 3, kq = (f & 7) << 2;
                cpa16(&ad[r * GST + kq], &he[(size_t)(i0 + r) * D + kc + kq]);
                cpa16(&bd[r * GST + kq], &W[(size_t)(nrow0 + r) * (2 * D) + koff + kc + kq]);
            }
            asm volatile("cp.async.commit_group;");
            asm volatile("cp.async.wait_group 1;");
        } else {
            asm volatile("cp.async.wait_group 0;");
        }
        __syncthreads();

        const float* ab = as + (ch & 1) * 128 * GST;
        const float* bb = bs + (ch & 1) * 128 * GST;
        #pragma unroll
        for (int kk = 0; kk < 32; kk += 2) {
            u64 av[8], bv[8];
            #pragma unroll
            for (int r = 0; r < 8; r++)
                av[r] = *(const u64*)&ab[(ty + 16 * r) * GST + kk];
            #pragma unroll
            for (int c = 0; c < 8; c++)
                bv[c] = *(const u64*)&bb[(tx + 16 * c) * GST + kk];
            #pragma unroll
            for (int r = 0; r < 8; r++)
                #pragma unroll
                for (int c = 0; c < 8; c++)
                    fma2(acc[r][c], av[r], bv[c]);
        }
        __syncthreads();
    }

    #pragma unroll
    for (int r = 0; r < 8; r++) {
        const size_t row = i0 + ty + 16 * r;
        float* dst = g_part + (size_t)kz * (N * 1024) + row * 1024 + n0;
        #pragma unroll
        for (int c = 0; c < 8; c++) {
            float2 f = upk(acc[r][c]);
            dst[tx + 16 * c] = f.x + f.y;
        }
    }
}

// ---------------------------------------------------------------------------
// Kernel 2: reduce 4 k-split partials -> g_u and g_vT (+bias). Deterministic.
// 128 CTAs x 256 threads x 4 float4.
// ---------------------------------------------------------------------------
__global__ __launch_bounds__(256) void reduce_kernel(const float* __restrict__ b)
{
    const int tid = threadIdx.x;
    #pragma unroll
    for (int e = 0; e < 4; e++) {
        const int idx4 = blockIdx.x * 1024 + e * 256 + tid;
        float4 s = *(const float4*)&g_part[(size_t)idx4 * 4];
        #pragma unroll
        for (int kz = 1; kz < 4; kz++) {
            float4 p = *(const float4*)&g_part[(size_t)kz * (N * 1024) + (size_t)idx4 * 4];
            s.x += p.x; s.y += p.y; s.z += p.z; s.w += p.w;
        }
        const int base = idx4 * 4;
        const int i = base >> 10;
        const int h = base & 1023;
        if (h < 512) {
            *(float4*)&g_u[(size_t)i * D + h] = s;
        } else {
            const int hh = h - 512;
            g_vT[(size_t)(hh + 0) * N + i] = s.x + b[hh + 0];
            g_vT[(size_t)(hh + 1) * N + i] = s.y + b[hh + 1];
            g_vT[(size_t)(hh + 2) * N + i] = s.z + b[hh + 2];
            g_vT[(size_t)(hh + 3) * N + i] = s.w + b[hh + 3];
        }
    }
}

// ---------------------------------------------------------------------------
// Kernel 3: pairwise + softmax, j-pair packed. CTA = 4 i-rows x 512 j,
// 256 threads (thread = 4i x j-pair {2t,2t+1}). v from g_vT rows (natural
// 8B pairs), u/w1 pre-duplicated as {x,x} u64 in smem. cp.async double-
// buffered 16-h v chunks.
// ---------------------------------------------------------------------------
#define PHCH 16

__global__ __launch_bounds__(256) void pairwise_kernel(
    const float* __restrict__ w1)
{
    extern __shared__ float sm[];
    float* v_s  = sm;                        // [2][PHCH][512]
    u64*  u2s   = (u64*)(sm + 2 * PHCH * 512);   // [4*512]
    u64*  w2s   = u2s + 4 * 512;                 // [512]
    float* p_s  = (float*)(w2s + 512);           // [4][512]
    float* inv_s = p_s + 4 * 512;                // [4]

    const int tid = threadIdx.x;
    const int i0 = blockIdx.x * 4;

    // duplicate-stage u (4 rows) and w1 as {x,x} pairs
    {
        const float* usrc = g_u + (size_t)i0 * D;
        #pragma unroll
        for (int e = 0; e < 8; e++) {
            const int m = tid * 8 + e;           // 0..2047
            const float f = usrc[m];
            u2s[m] = pk(f, f);
        }
        #pragma unroll
        for (int e = 0; e < 2; e++) {
            const int m = tid * 2 + e;           // 0..511
            const float f = w1[m];
            w2s[m] = pk(f, f);
        }
    }

    // prologue: v chunk 0 (16 h-rows x 512 j)
    for (int m = tid; m < PHCH * 128; m += 256) {
        const int r = m >> 7, c4 = (m & 127) << 2;
        cpa16(v_s + r * 512 + c4, g_vT + (size_t)r * N + c4);
    }
    asm volatile("cp.async.commit_group;");

    u64 acc[4] = {};

    for (int ch = 0; ch < D / PHCH; ch++) {
        if (ch + 1 < D / PHCH) {
            float* buf = v_s + ((ch + 1) & 1) * PHCH * 512;
            const float* src = g_vT + (size_t)(ch + 1) * PHCH * N;
            for (int m = tid; m < PHCH * 128; m += 256) {
                const int r = m >> 7, c4 = (m & 127) << 2;
                cpa16(buf + r * 512 + c4, src + (size_t)r * N + c4);
            }
            asm volatile("cp.async.commit_group;");
            asm volatile("cp.async.wait_group 1;");
        } else {
            asm volatile("cp.async.wait_group 0;");
        }
        __syncthreads();

        const float* vb = v_s + (ch & 1) * PHCH * 512;
        const int g0 = ch * PHCH;
        #pragma unroll
        for (int h = 0; h < PHCH; h++) {
            const u64 vv = *(const u64*)&vb[h * 512 + 2 * tid];
            const u64 ww = w2s[g0 + h];
            #pragma unroll
            for (int i = 0; i < 4; i++) {
                const u64 uu = u2s[i * 512 + g0 + h];
                u64 t = add2(uu, vv);
                float2 f = upk(t);
                fma2(acc[i], pk(fmaxf(f.x, 0.f), fmaxf(f.y, 0.f)), ww);
            }
        }
        __syncthreads();
    }

    // acc[i] holds (p[i][2t], p[i][2t+1])
    #pragma unroll
    for (int i = 0; i < 4; i++)
        ((u64*)(p_s + i * 512))[tid] = acc[i];
    __syncthreads();

    // softmax: warps 0..3 handle rows 0..3
    const int warp = tid >> 5, lane = tid & 31;
    if (warp < 4) {
        float* prow = p_s + warp * 512;
        float m = -1e30f;
        for (int j = lane; j < N; j += 32) m = fmaxf(m, prow[j]);
        #pragma unroll
        for (int o = 16; o; o >>= 1) m = fmaxf(m, __shfl_xor_sync(0xffffffffu, m, o));
        float s = 0.f;
        for (int j = lane; j < N; j += 32) {
            float e = __expf(prow[j] - m);
            prow[j] = e;
            s += e;
        }
        #pragma unroll
        for (int o = 16; o; o >>= 1) s += __shfl_xor_sync(0xffffffffu, s, o);
        if (lane == 0) inv_s[warp] = 1.f / s;
    }
    __syncthreads();

    #pragma unroll
    for (int e = 0; e < 2; e++) {
        const int m = tid + 256 * e;            // 0..511 over 4x128 f4
        const int i = m >> 7, jj = m & 127;
        float4 v = ((const float4*)(p_s + i * 512))[jj];
        const float s = inv_s[i];
        v.x *= s; v.y *= s; v.z *= s; v.w *= s;
        ((float4*)(g_a + (size_t)(i0 + i) * N))[jj] = v;
    }
}

// ---------------------------------------------------------------------------
// Kernel 4: out = a @ he, c-pair packed. Tile 32i x 64c, 128 threads
// (thread = 4i x 2 c-pairs). b = he natural rows via cp.async; a duplicated
// {x,x} in smem. Double-buffered 32-k chunks. grid (8,16) = 128 CTAs.
// ---------------------------------------------------------------------------
#define OHST 68

__global__ __launch_bounds__(128) void out_gemm_kernel(
    const float* __restrict__ he, float* __restrict__ out)
{
    __shared__ float he_s[2][32 * OHST];  // [k][c] rows, 64 used + pad
    __shared__ u64  a2s[2][32 * 32];      // [i][k] duplicated pairs

    const int c0 = blockIdx.x * 64;
    const int i0 = blockIdx.y * 32;
    const int tid = threadIdx.x;
    const int tx = tid & 15;
    const int ty = tid >> 4;              // 0..7

    // a-val loader mapping: row = tid>>2 (0..31), kq = (tid&3)*8
    const int ar = tid >> 2;
    const int akq = (tid & 3) << 3;

    float areg[8];

    // prologue: a(0) + he(0)
    {
        float4 v0 = *(const float4*)&g_a[(size_t)(i0 + ar) * N + akq];
        float4 v1 = *(const float4*)&g_a[(size_t)(i0 + ar) * N + akq + 4];
        areg[0] = v0.x; areg[1] = v0.y; areg[2] = v0.z; areg[3] = v0.w;
        areg[4] = v1.x; areg[5] = v1.y; areg[6] = v1.z; areg[7] = v1.w;
        #pragma unroll
        for (int e = 0; e < 8; e++)
            a2s[0][ar * 32 + akq + e] = pk(areg[e], areg[e]);
        for (int m = tid; m < 32 * 16; m += 128) {
            const int k = m >> 4, cq = (m & 15) << 2;
            cpa16(&he_s[0][k * OHST + cq], &he[(size_t)k * D + c0 + cq]);
        }
        asm volatile("cp.async.commit_group;");
    }

    u64 acc[4][2] = {};

    for (int ch = 0; ch < 16; ch++) {
        if (ch + 1 < 16) {
            const int k0 = (ch + 1) * 32;
            float4 v0 = *(const float4*)&g_a[(size_t)(i0 + ar) * N + k0 + akq];
            float4 v1 = *(const float4*)&g_a[(size_t)(i0 + ar) * N + k0 + akq + 4];
            areg[0] = v0.x; areg[1] = v0.y; areg[2] = v0.z; areg[3] = v0.w;
            areg[4] = v1.x; areg[5] = v1.y; areg[6] = v1.z; areg[7] = v1.w;
            float* hd = he_s[(ch + 1) & 1];
            for (int m = tid; m < 32 * 16; m += 128) {
                const int k = m >> 4, cq = (m & 15) << 2;
                cpa16(&hd[k * OHST + cq], &he[(size_t)(k0 + k) * D + c0 + cq]);
            }
            asm volatile("cp.async.commit_group;");
            asm volatile("cp.async.wait_group 1;");
        } else {
            asm volatile("cp.async.wait_group 0;");
        }
        __syncthreads();

        const float* hb = he_s[ch & 1];
        const u64* ab = a2s[ch & 1];
        #pragma unroll
        for (int k = 0; k < 32; k++) {
            ulonglong2 bb = *(const ulonglong2*)&hb[k * OHST + 4 * tx];
            #pragma unroll
            for (int r = 0; r < 4; r++) {
                const u64 aa = ab[(ty + 8 * r) * 32 + k];
                fma2(acc[r][0], aa, bb.x);
                fma2(acc[r][1], aa, bb.y);
            }
        }

        if (ch + 1 < 16) {
            #pragma unroll
            for (int e = 0; e < 8; e++)
                a2s[(ch + 1) & 1][ar * 32 + akq + e] = pk(areg[e], areg[e]);
        }
        __syncthreads();
    }

    #pragma unroll
    for (int r = 0; r < 4; r++) {
        float2 f0 = upk(acc[r][0]);
        float2 f1 = upk(acc[r][1]);
        float4 o = make_float4(f0.x, f0.y, f1.x, f1.y);
        *(float4*)&out[(size_t)(i0 + ty + 8 * r) * D + c0 + 4 * tx] = o;
    }
}

// ---------------------------------------------------------------------------
extern "C" void kernel_launch(void* const* d_in, const int* in_sizes, int n_in,
                              void* d_out, int out_size)
{
    const float* he  = (const float*)d_in[0];   // (512, 512)
    const float* W0w = (const float*)d_in[1];   // (512, 1024)
    const float* W0b = (const float*)d_in[2];   // (512,)
    const float* W1w = (const float*)d_in[3];   // (1, 512)
    // d_in[4] = W1_b: softmax shift-invariant -> unused
    float* out = (float*)d_out;

    const size_t smemG = (size_t)(4 * 128 * GST) * sizeof(float);       // ~73.7KB
    const size_t smemP = (size_t)(2 * PHCH * 512) * sizeof(float)       // v
                       + (size_t)(4 * 512 + 512) * sizeof(u64)          // u2s+w2s
                       + (size_t)(4 * 512 + 8) * sizeof(float);         // p_s+inv
    cudaFuncSetAttribute(uv_gemm_kernel,
                         cudaFuncAttributeMaxDynamicSharedMemorySize, (int)smemG);
    cudaFuncSetAttribute(pairwise_kernel,
                         cudaFuncAttributeMaxDynamicSharedMemorySize, (int)smemP);

    dim3 gG(8, 4, 4);                            // 128 CTAs x 256 thr
    uv_gemm_kernel<<<gG, 256, smemG>>>(he, W0w);

    reduce_kernel<<<128, 256>>>(W0b);

    pairwise_kernel<<<N / 4, 256, smemP>>>(W1w); // 128 CTAs x 256 thr

    dim3 gC(8, 16);                              // 128 CTAs x 128 thr
    out_gemm_kernel<<<gC, 128>>>(he, out);
}